// round 5
// baseline (speedup 1.0000x reference)
#include <cuda_runtime.h>
#include <cstdint>
#include <cstddef>

#define DD 256
#define PP 512
#define TT 65536
#define LSEQ 2048
#define EPSL 1e-5f

__device__ float g_wcat[DD * 768];          // [o][tap*256+c], tf32
__device__ float g_wq[512 * DD];            // tf32
__device__ float g_wo[DD * 512];            // tf32
__device__ float g_xln[(size_t)TT * DD];    // conv raw -> LN'd tf32
__device__ float g_scr[(size_t)TT * DD];    // out-GEMM scratch
__device__ float g_att[(size_t)TT * 512];   // attn out raw fp32
__device__ float g_k[8 * PP * 64];          // [h][w][d], scaled 1/8, tf32
__device__ float g_vT[8 * 64 * PP];         // [h][d][w], tf32

__device__ __forceinline__ uint32_t s2u(const void* p) {
    uint32_t a;
    asm("{ .reg .u64 t; cvta.to.shared.u64 t, %1; cvt.u32.u64 %0, t; }" : "=r"(a) : "l"(p));
    return a;
}
__device__ __forceinline__ float ftf(float x) {
    uint32_t u;
    asm("cvt.rna.tf32.f32 %0, %1;" : "=r"(u) : "f"(x));
    return __uint_as_float(u);
}
__device__ __forceinline__ float4 ftf4(float4 v) {
    v.x = ftf(v.x); v.y = ftf(v.y); v.z = ftf(v.z); v.w = ftf(v.w);
    return v;
}
__device__ __forceinline__ void mma8(float* c, const uint32_t* a, const uint32_t* b) {
    asm volatile(
        "mma.sync.aligned.m16n8k8.row.col.f32.tf32.tf32.f32 "
        "{%0,%1,%2,%3}, {%4,%5,%6,%7}, {%8,%9}, {%0,%1,%2,%3};"
        : "+f"(c[0]), "+f"(c[1]), "+f"(c[2]), "+f"(c[3])
        : "r"(a[0]), "r"(a[1]), "r"(a[2]), "r"(a[3]), "r"(b[0]), "r"(b[1]));
}
__device__ __forceinline__ void ldsm4(uint32_t* r, uint32_t addr) {
    asm volatile("ldmatrix.sync.aligned.m8n8.x4.shared.b16 {%0,%1,%2,%3}, [%4];"
        : "=r"(r[0]), "=r"(r[1]), "=r"(r[2]), "=r"(r[3]) : "r"(addr));
}

// ---------- K0: weight prep ----------
__global__ void __launch_bounds__(256) k_prep(const float* __restrict__ conv_w,
                                              const float* __restrict__ wq,
                                              const float* __restrict__ wout) {
    int idx = blockIdx.x * 256 + threadIdx.x;
    if (idx < DD * 768) {
        int o = idx / 768, col = idx % 768;
        g_wcat[idx] = ftf(conv_w[o * 768 + (col & 255) * 3 + (col >> 8)]);
    }
    if (idx < 512 * DD) g_wq[idx] = ftf(wq[idx]);
    if (idx < DD * 512) g_wo[idx] = ftf(wout[idx]);
}

__device__ __forceinline__ float2 bsum2(float a, float b, float* red) {
    #pragma unroll
    for (int o = 16; o; o >>= 1) {
        a += __shfl_xor_sync(0xffffffffu, a, o);
        b += __shfl_xor_sync(0xffffffffu, b, o);
    }
    __syncthreads();
    if ((threadIdx.x & 31) == 0) {
        red[threadIdx.x >> 5] = a;
        red[(threadIdx.x >> 5) + 8] = b;
    }
    __syncthreads();
    a = 0.f; b = 0.f;
    #pragma unroll
    for (int k = 0; k < 8; k++) { a += red[k]; b += red[k + 8]; }
    return make_float2(a, b);
}

// ---------- K1: pattern double-LN + kv projection ----------
__global__ void __launch_bounds__(256) k_patkv(const float* __restrict__ pattern,
                                               const float* __restrict__ wkv) {
    __shared__ float sp[8][DD];
    __shared__ float red[16];
    int r0 = blockIdx.x * 8, tid = threadIdx.x;
    for (int r = 0; r < 8; r++) {
        float v = pattern[(size_t)(r0 + r) * DD + tid];
        for (int it = 0; it < 2; it++) {
            float2 s = bsum2(v, v * v, red);
            float mu = s.x * (1.f / DD);
            v = (v - mu) * rsqrtf(s.y * (1.f / DD) - mu * mu + EPSL);
        }
        sp[r][tid] = v;
    }
    __syncthreads();
    for (int m = 0; m < 4; m++) {
        int j = m * 256 + tid;
        float acc[8];
        #pragma unroll
        for (int r = 0; r < 8; r++) acc[r] = 0.f;
        const float* wr = wkv + (size_t)j * DD;
        for (int i = 0; i < DD; i++) {
            float w = wr[i];
            #pragma unroll
            for (int r = 0; r < 8; r++) acc[r] += w * sp[r][i];
        }
        int h = j >> 7, e = j & 127;
        if (e < 64) {
            #pragma unroll
            for (int r = 0; r < 8; r++)
                g_k[((size_t)h * PP + r0 + r) * 64 + e] = ftf(0.125f * acc[r]);
        } else {
            #pragma unroll
            for (int r = 0; r < 8; r++)
                g_vT[((size_t)h * 64 + e - 64) * PP + r0 + r] = ftf(acc[r]);
        }
    }
}

// ---------- generic MMA GEMM (mode 0: conv taps+mask+ftf; mode 2: ftf) ----------
__global__ void __launch_bounds__(256) k_gemm(const float* __restrict__ A,
                                              const float* __restrict__ B,
                                              float* __restrict__ C,
                                              int K, int lda, int ldc, int mode) {
    extern __shared__ float sm[];
    float* As = sm;               // [128][36]
    float* Bs = sm + 128 * 36;    // [128][36]
    int tid = threadIdx.x, lane = tid & 31, warp = tid >> 5;
    int r8 = lane & 7, g = lane >> 3;
    int qr = lane >> 2, qc = lane & 3;
    int wm = warp >> 1, wn = warp & 1;
    int t0 = blockIdx.x * 128, n0 = blockIdx.y * 128;
    int seq0 = t0 & ~(LSEQ - 1);

    uint32_t a_base = s2u(As) + ((wm * 32 + r8 + (g & 1) * 8) * 36 + (g >> 1) * 4) * 4;
    uint32_t b_base = s2u(Bs) + ((wn * 64 + r8 + (g >> 1) * 8) * 36 + (g & 1) * 4) * 4;

    float cacc[2][8][4];
    #pragma unroll
    for (int mt = 0; mt < 2; mt++)
        #pragma unroll
        for (int nt = 0; nt < 8; nt++)
            #pragma unroll
            for (int i = 0; i < 4; i++) cacc[mt][nt][i] = 0.f;

    for (int kc = 0; kc < K; kc += 32) {
        #pragma unroll
        for (int i = tid; i < 1024; i += 256) {
            int r = i >> 3, cc = i & 7;
            float4 v;
            if (mode == 0) {
                int t = t0 + r + (kc >> 8) - 2;
                if (t >= seq0)
                    v = ftf4(*(const float4*)(A + (size_t)t * 256 + (kc & 255) + cc * 4));
                else
                    v = make_float4(0.f, 0.f, 0.f, 0.f);
            } else {
                v = ftf4(*(const float4*)(A + (size_t)(t0 + r) * lda + kc + cc * 4));
            }
            *(float4*)(As + r * 36 + cc * 4) = v;
            *(float4*)(Bs + r * 36 + cc * 4) =
                *(const float4*)(B + (size_t)(n0 + r) * K + kc + cc * 4);
        }
        __syncthreads();
        #pragma unroll
        for (int ks = 0; ks < 4; ks++) {
            uint32_t a0[4], a1[4], bb[4][4];
            ldsm4(a0, a_base + ks * 32);
            ldsm4(a1, a_base + 16 * 36 * 4 + ks * 32);
            #pragma unroll
            for (int n2 = 0; n2 < 4; n2++) ldsm4(bb[n2], b_base + n2 * 16 * 36 * 4 + ks * 32);
            #pragma unroll
            for (int n2 = 0; n2 < 4; n2++) {
                mma8(cacc[0][n2 * 2],     a0, &bb[n2][0]);
                mma8(cacc[0][n2 * 2 + 1], a0, &bb[n2][2]);
                mma8(cacc[1][n2 * 2],     a1, &bb[n2][0]);
                mma8(cacc[1][n2 * 2 + 1], a1, &bb[n2][2]);
            }
        }
        __syncthreads();
    }
    #pragma unroll
    for (int mt = 0; mt < 2; mt++)
        #pragma unroll
        for (int nt = 0; nt < 8; nt++) {
            int r = t0 + wm * 32 + mt * 16 + qr;
            int col = n0 + wn * 64 + nt * 8 + qc * 2;
            *(float2*)(C + (size_t)r * ldc + col) =
                make_float2(cacc[mt][nt][0], cacc[mt][nt][1]);
            *(float2*)(C + (size_t)(r + 8) * ldc + col) =
                make_float2(cacc[mt][nt][2], cacc[mt][nt][3]);
        }
}

// ---------- conv epilogue (in-place on g_xln) ----------
__global__ void __launch_bounds__(256) k_convln(const float* __restrict__ x,
                                                const float* __restrict__ cbias) {
    __shared__ float red[16];
    int tid = threadIdx.x;
    float bv = cbias[tid];
    for (int r = 0; r < 8; r++) {
        size_t row = (size_t)blockIdx.x * 8 + r;
        float y = g_xln[row * DD + tid] + bv + x[row * DD + tid];
        y = y > 0.f ? y : 0.01f * y;
        float2 s = bsum2(y, y * y, red);
        float mu = s.x * (1.f / DD);
        float inv = rsqrtf(s.y * (1.f / DD) - mu * mu + EPSL);
        g_xln[row * DD + tid] = ftf((y - mu) * inv);
    }
}

// ---------- final epilogue ----------
__global__ void __launch_bounds__(256) k_outln(const float* __restrict__ bout,
                                               float* __restrict__ out) {
    __shared__ float red[16];
    int tid = threadIdx.x;
    float bv = bout[tid];
    for (int r = 0; r < 8; r++) {
        size_t row = (size_t)blockIdx.x * 8 + r;
        float y = g_scr[row * DD + tid] + bv;
        float2 s = bsum2(y, y * y, red);
        float mu = s.x * (1.f / DD);
        float inv = rsqrtf(s.y * (1.f / DD) - mu * mu + EPSL);
        out[row * DD + tid] = (y - mu) * inv;
    }
}

// ---------- fused q-proj + attention, 512 threads ----------
__global__ void __launch_bounds__(512) k_attn() {
    extern __shared__ float sm[];
    float* Aq = sm;                   // [128][68]  q (tf32)
    float* Bk = Aq + 128 * 68;        // [128][68]
    float* Bv = Bk + 128 * 68;        // [64][132]
    float* P  = Bv + 64 * 132;        // [128][132]
    float* rs = P + 128 * 132;        // [128]
    float* StA = P;                   // staging [128][36] (aliases P, q-phase only)
    float* StB = P + 128 * 36;        // staging [64][36]
    int tid = threadIdx.x, lane = tid & 31, warp = tid >> 5;
    int r8 = lane & 7, g = lane >> 3;
    int qr = lane >> 2, qc = lane & 3;
    int wm = warp >> 2, wn = warp & 3;
    int t0 = blockIdx.x * 128, h = blockIdx.y;

    if (tid < 128) rs[tid] = 0.f;

    // ---- q = xln @ wq_h^T ----
    uint32_t sa = s2u(StA) + ((wm * 32 + r8 + (g & 1) * 8) * 36 + (g >> 1) * 4) * 4;
    uint32_t sb = s2u(StB) + ((wn * 16 + r8 + (g >> 1) * 8) * 36 + (g & 1) * 4) * 4;
    float qa[2][2][4];
    #pragma unroll
    for (int mt = 0; mt < 2; mt++)
        #pragma unroll
        for (int nt = 0; nt < 2; nt++)
            #pragma unroll
            for (int i = 0; i < 4; i++) qa[mt][nt][i] = 0.f;

    for (int kc = 0; kc < 256; kc += 32) {
        __syncthreads();
        for (int i = tid; i < 1024; i += 512) {
            int r = i >> 3, cc = i & 7;
            *(float4*)(StA + r * 36 + cc * 4) =
                *(const float4*)(g_xln + (size_t)(t0 + r) * 256 + kc + cc * 4);
        }
        for (int i = tid; i < 512; i += 512) {
            int r = i >> 3, cc = i & 7;
            *(float4*)(StB + r * 36 + cc * 4) =
                *(const float4*)(g_wq + (size_t)(h * 64 + r) * 256 + kc + cc * 4);
        }
        __syncthreads();
        #pragma unroll
        for (int ks = 0; ks < 4; ks++) {
            uint32_t a0[4], a1[4], bb[4];
            ldsm4(a0, sa + ks * 32);
            ldsm4(a1, sa + 16 * 36 * 4 + ks * 32);
            ldsm4(bb, sb + ks * 32);
            mma8(qa[0][0], a0, &bb[0]);
            mma8(qa[0][1], a0, &bb[2]);
            mma8(qa[1][0], a1, &bb[0]);
            mma8(qa[1][1], a1, &bb[2]);
        }
    }
    __syncthreads();
    #pragma unroll
    for (int mt = 0; mt < 2; mt++)
        #pragma unroll
        for (int nt = 0; nt < 2; nt++) {
            int r = wm * 32 + mt * 16 + qr;
            int col = wn * 16 + nt * 8 + qc * 2;
            *(float2*)(Aq + r * 68 + col) =
                make_float2(ftf(qa[mt][nt][0]), ftf(qa[mt][nt][1]));
            *(float2*)(Aq + (r + 8) * 68 + col) =
                make_float2(ftf(qa[mt][nt][2]), ftf(qa[mt][nt][3]));
        }

    // ---- main loop over 4 pattern chunks ----
    uint32_t sqa = s2u(Aq) + ((wm * 32 + r8 + (g & 1) * 8) * 68 + (g >> 1) * 4) * 4;
    uint32_t sqb = s2u(Bk) + ((wn * 32 + r8 + (g >> 1) * 8) * 68 + (g & 1) * 4) * 4;
    uint32_t spa = s2u(P)  + ((wm * 32 + r8 + (g & 1) * 8) * 132 + (g >> 1) * 4) * 4;
    uint32_t spb = s2u(Bv) + ((wn * 16 + r8 + (g >> 1) * 8) * 132 + (g & 1) * 4) * 4;

    float oacc[2][2][4];
    #pragma unroll
    for (int mt = 0; mt < 2; mt++)
        #pragma unroll
        for (int nt = 0; nt < 2; nt++)
            #pragma unroll
            for (int i = 0; i < 4; i++) oacc[mt][nt][i] = 0.f;

    for (int c = 0; c < 4; c++) {
        __syncthreads();
        for (int i = tid; i < 2048; i += 512) {
            int r = i >> 4, cc = i & 15;
            *(float4*)(Bk + r * 68 + cc * 4) =
                *(const float4*)(g_k + ((size_t)h * PP + c * 128 + r) * 64 + cc * 4);
        }
        for (int i = tid; i < 2048; i += 512) {
            int r = i >> 5, cc = i & 31;
            *(float4*)(Bv + r * 132 + cc * 4) =
                *(const float4*)(g_vT + ((size_t)h * 64 + r) * PP + c * 128 + cc * 4);
        }
        __syncthreads();

        float s[2][4][4];
        #pragma unroll
        for (int mt = 0; mt < 2; mt++)
            #pragma unroll
            for (int nt = 0; nt < 4; nt++)
                #pragma unroll
                for (int i = 0; i < 4; i++) s[mt][nt][i] = 0.f;
        #pragma unroll
        for (int ks = 0; ks < 8; ks++) {
            uint32_t a0[4], a1[4], b0[4], b1[4];
            ldsm4(a0, sqa + ks * 32);
            ldsm4(a1, sqa + 16 * 68 * 4 + ks * 32);
            ldsm4(b0, sqb + ks * 32);
            ldsm4(b1, sqb + 16 * 68 * 4 + ks * 32);
            mma8(s[0][0], a0, &b0[0]); mma8(s[0][1], a0, &b0[2]);
            mma8(s[0][2], a0, &b1[0]); mma8(s[0][3], a0, &b1[2]);
            mma8(s[1][0], a1, &b0[0]); mma8(s[1][1], a1, &b0[2]);
            mma8(s[1][2], a1, &b1[0]); mma8(s[1][3], a1, &b1[2]);
        }

        #pragma unroll
        for (int mt = 0; mt < 2; mt++) {
            int r = wm * 32 + mt * 16 + qr;
            float sum0 = 0.f, sum1 = 0.f;
            #pragma unroll
            for (int nt = 0; nt < 4; nt++) {
                float e0 = __expf(s[mt][nt][0]);
                float e1 = __expf(s[mt][nt][1]);
                float e2 = __expf(s[mt][nt][2]);
                float e3 = __expf(s[mt][nt][3]);
                sum0 += e0 + e1;
                sum1 += e2 + e3;
                int col = wn * 32 + nt * 8 + qc * 2;
                *(float2*)(P + r * 132 + col) = make_float2(ftf(e0), ftf(e1));
                *(float2*)(P + (r + 8) * 132 + col) = make_float2(ftf(e2), ftf(e3));
            }
            sum0 += __shfl_xor_sync(0xffffffffu, sum0, 1);
            sum0 += __shfl_xor_sync(0xffffffffu, sum0, 2);
            sum1 += __shfl_xor_sync(0xffffffffu, sum1, 1);
            sum1 += __shfl_xor_sync(0xffffffffu, sum1, 2);
            if (qc == 0) {
                atomicAdd(&rs[r], sum0);
                atomicAdd(&rs[r + 8], sum1);
            }
        }
        __syncthreads();

        #pragma unroll
        for (int ks = 0; ks < 16; ks++) {
            uint32_t a0[4], a1[4], bb[4];
            ldsm4(a0, spa + ks * 32);
            ldsm4(a1, spa + 16 * 132 * 4 + ks * 32);
            ldsm4(bb, spb + ks * 32);
            mma8(oacc[0][0], a0, &bb[0]);
            mma8(oacc[0][1], a0, &bb[2]);
            mma8(oacc[1][0], a1, &bb[0]);
            mma8(oacc[1][1], a1, &bb[2]);
        }
    }

    #pragma unroll
    for (int mt = 0; mt < 2; mt++)
        #pragma unroll
        for (int nt = 0; nt < 2; nt++) {
            int r = wm * 32 + mt * 16 + qr;
            int col = wn * 16 + nt * 8 + qc * 2;
            float i0 = 1.f / rs[r], i1 = 1.f / rs[r + 8];
            *(float2*)(g_att + (size_t)(t0 + r) * 512 + h * 64 + col) =
                make_float2(oacc[mt][nt][0] * i0, oacc[mt][nt][1] * i0);
            *(float2*)(g_att + (size_t)(t0 + r + 8) * 512 + h * 64 + col) =
                make_float2(oacc[mt][nt][2] * i1, oacc[mt][nt][3] * i1);
        }
}

extern "C" void kernel_launch(void* const* d_in, const int* in_sizes, int n_in,
                              void* d_out, int out_size) {
    const float* x      = (const float*)d_in[0];
    const float* conv_w = (const float*)d_in[1];
    const float* conv_b = (const float*)d_in[2];
    const float* pat    = (const float*)d_in[3];
    const float* wq     = (const float*)d_in[4];
    const float* wkv    = (const float*)d_in[5];
    const float* wout   = (const float*)d_in[6];
    const float* bout   = (const float*)d_in[7];
    float* out = (float*)d_out;

    const int GEMM_SMEM = 2 * 128 * 36 * 4;                          // 36864
    const int ATTN_SMEM = (128*68 + 128*68 + 64*132 + 128*132 + 128) * 4;  // 171520
    cudaFuncSetAttribute(k_attn, cudaFuncAttributeMaxDynamicSharedMemorySize, ATTN_SMEM);

    float* g_wcat_p; cudaGetSymbolAddress((void**)&g_wcat_p, g_wcat);
    float* g_wo_p;   cudaGetSymbolAddress((void**)&g_wo_p, g_wo);
    float* g_xln_p;  cudaGetSymbolAddress((void**)&g_xln_p, g_xln);
    float* g_scr_p;  cudaGetSymbolAddress((void**)&g_scr_p, g_scr);
    float* g_att_p;  cudaGetSymbolAddress((void**)&g_att_p, g_att);

    k_prep<<<768, 256>>>(conv_w, wq, wout);
    k_patkv<<<64, 256>>>(pat, wkv);
    k_gemm<<<dim3(512, 2), 256, GEMM_SMEM>>>(x, g_wcat_p, g_xln_p, 768, 256, 256, 0);
    k_convln<<<8192, 256>>>(x, conv_b);
    k_attn<<<dim3(512, 8), 512, ATTN_SMEM>>>();
    k_gemm<<<dim3(512, 2), 256, GEMM_SMEM>>>(g_att_p, g_wo_p, g_scr_p, 512, 512, 256, 2);
    k_outln<<<8192, 256>>>(bout, out);
}

// round 7
// speedup vs baseline: 1.2360x; 1.2360x over previous
#include <cuda_runtime.h>
#include <cstdint>
#include <cstddef>

#define DD 256
#define PP 512
#define TT 65536
#define LSEQ 2048
#define EPSL 1e-5f

__device__ float g_wcat[DD * 768];
__device__ float g_wq[512 * DD];
__device__ float g_wo[DD * 512];
__device__ float g_xr[(size_t)TT * DD];     // ftf(x)
__device__ float g_xln[(size_t)TT * DD];    // conv+LN, tf32
__device__ float g_q[(size_t)TT * 512];     // q, tf32
__device__ float g_att[(size_t)TT * 512];   // attn out, tf32
__device__ float g_k[8 * PP * 64];
__device__ float g_vT[8 * 64 * PP];

__device__ __forceinline__ uint32_t s2u(const void* p) {
    uint32_t a;
    asm("{ .reg .u64 t; cvta.to.shared.u64 t, %1; cvt.u32.u64 %0, t; }" : "=r"(a) : "l"(p));
    return a;
}
__device__ __forceinline__ float ftf(float x) {
    uint32_t u;
    asm("cvt.rna.tf32.f32 %0, %1;" : "=r"(u) : "f"(x));
    return __uint_as_float(u);
}
__device__ __forceinline__ float4 ftf4(float4 v) {
    v.x = ftf(v.x); v.y = ftf(v.y); v.z = ftf(v.z); v.w = ftf(v.w);
    return v;
}
__device__ __forceinline__ void mma8(float* c, const uint32_t* a, const uint32_t* b) {
    asm volatile(
        "mma.sync.aligned.m16n8k8.row.col.f32.tf32.tf32.f32 "
        "{%0,%1,%2,%3}, {%4,%5,%6,%7}, {%8,%9}, {%0,%1,%2,%3};"
        : "+f"(c[0]), "+f"(c[1]), "+f"(c[2]), "+f"(c[3])
        : "r"(a[0]), "r"(a[1]), "r"(a[2]), "r"(a[3]), "r"(b[0]), "r"(b[1]));
}
__device__ __forceinline__ void ldsm4(uint32_t* r, uint32_t addr) {
    asm volatile("ldmatrix.sync.aligned.m8n8.x4.shared.b16 {%0,%1,%2,%3}, [%4];"
        : "=r"(r[0]), "=r"(r[1]), "=r"(r[2]), "=r"(r[3]) : "r"(addr));
}
__device__ __forceinline__ void cpa16(uint32_t dst, const float* src) {
    asm volatile("cp.async.ca.shared.global [%0], [%1], 16;" :: "r"(dst), "l"(src));
}
__device__ __forceinline__ void cpa16p(uint32_t dst, const float* src, int ok) {
    int sz = ok ? 16 : 0;
    asm volatile("cp.async.ca.shared.global [%0], [%1], 16, %2;" :: "r"(dst), "l"(src), "r"(sz));
}
#define CPCOMMIT() asm volatile("cp.async.commit_group;" ::: "memory")
#define FB(p) __float_as_uint(p)

// ---------- K0: weight prep ----------
__global__ void __launch_bounds__(256) k_prep(const float* __restrict__ conv_w,
                                              const float* __restrict__ wq,
                                              const float* __restrict__ wout) {
    int idx = blockIdx.x * 256 + threadIdx.x;
    if (idx < DD * 768) {
        int o = idx / 768, col = idx % 768;
        g_wcat[idx] = ftf(conv_w[o * 768 + (col & 255) * 3 + (col >> 8)]);
    }
    if (idx < 512 * DD) g_wq[idx] = ftf(wq[idx]);
    if (idx < DD * 512) g_wo[idx] = ftf(wout[idx]);
}

// ---------- K0b: pre-round x ----------
__global__ void __launch_bounds__(256) k_prepx(const float* __restrict__ x) {
    size_t i = ((size_t)blockIdx.x * 256 + threadIdx.x) * 4;
    *(float4*)(g_xr + i) = ftf4(*(const float4*)(x + i));
}

__device__ __forceinline__ float2 bsum2(float a, float b, float* red) {
    #pragma unroll
    for (int o = 16; o; o >>= 1) {
        a += __shfl_xor_sync(0xffffffffu, a, o);
        b += __shfl_xor_sync(0xffffffffu, b, o);
    }
    __syncthreads();
    if ((threadIdx.x & 31) == 0) {
        red[threadIdx.x >> 5] = a;
        red[(threadIdx.x >> 5) + 8] = b;
    }
    __syncthreads();
    a = 0.f; b = 0.f;
    #pragma unroll
    for (int k = 0; k < 8; k++) { a += red[k]; b += red[k + 8]; }
    return make_float2(a, b);
}

// ---------- K1: pattern double-LN + kv ----------
__global__ void __launch_bounds__(256) k_patkv(const float* __restrict__ pattern,
                                               const float* __restrict__ wkv) {
    __shared__ float sp[8][DD];
    __shared__ float red[16];
    int r0 = blockIdx.x * 8, tid = threadIdx.x;
    for (int r = 0; r < 8; r++) {
        float v = pattern[(size_t)(r0 + r) * DD + tid];
        for (int it = 0; it < 2; it++) {
            float2 s = bsum2(v, v * v, red);
            float mu = s.x * (1.f / DD);
            v = (v - mu) * rsqrtf(s.y * (1.f / DD) - mu * mu + EPSL);
        }
        sp[r][tid] = v;
    }
    __syncthreads();
    for (int m = 0; m < 4; m++) {
        int j = m * 256 + tid;
        float acc[8];
        #pragma unroll
        for (int r = 0; r < 8; r++) acc[r] = 0.f;
        const float* wr = wkv + (size_t)j * DD;
        for (int i = 0; i < DD; i++) {
            float w = wr[i];
            #pragma unroll
            for (int r = 0; r < 8; r++) acc[r] += w * sp[r][i];
        }
        int h = j >> 7, e = j & 127;
        if (e < 64) {
            #pragma unroll
            for (int r = 0; r < 8; r++)
                g_k[((size_t)h * PP + r0 + r) * 64 + e] = ftf(0.125f * acc[r]);
        } else {
            #pragma unroll
            for (int r = 0; r < 8; r++)
                g_vT[((size_t)h * 64 + e - 64) * PP + r0 + r] = ftf(acc[r]);
        }
    }
}

// ---------- prefetch one K-chunk into staging buffer b ----------
__device__ __forceinline__ void gemm_prefetch(const float* A, const float* B,
                                              uint32_t as_u, uint32_t bs_u,
                                              int c, int K, int t0, int n0,
                                              int seq0, int mode, int tid) {
    int b = c & 1, kc = c * 32;
    uint32_t ad = as_u + b * 128 * 36 * 4;
    uint32_t bd = bs_u + b * 256 * 36 * 4;
    if (mode == 0) {
        for (int i = tid; i < 1024; i += 512) {
            int r = i >> 3, cc = i & 7;
            int t = t0 + r + (kc >> 8) - 2;
            int ok = t >= seq0;
            const float* s = A + (size_t)(ok ? t : seq0) * 256 + (kc & 255) + cc * 4;
            cpa16p(ad + (r * 36 + cc * 4) * 4, s, ok);
        }
    } else {
        for (int i = tid; i < 1024; i += 512) {
            int r = i >> 3, cc = i & 7;
            cpa16(ad + (r * 36 + cc * 4) * 4, A + (size_t)(t0 + r) * K + kc + cc * 4);
        }
    }
    for (int i = tid; i < 2048; i += 512) {
        int r = i >> 3, cc = i & 7;
        cpa16(bd + (r * 36 + cc * 4) * 4, B + (size_t)(n0 + r) * K + kc + cc * 4);
    }
    CPCOMMIT();
}

// ---------- fused GEMM: C[128 x 256] = A[128,K] @ B[256,K]^T (+ LN epilogue) ----------
// mode 0: conv (A=g_xr taps/mask; +cbias +x residual +leaky +LN -> g_xln ftf)
// mode 1: q    (plain, ftf out)
// mode 2: out  (+bout +LN -> out raw)
__global__ void __launch_bounds__(512, 1) k_gemm(const float* __restrict__ A,
                                                 const float* __restrict__ B,
                                                 const float* __restrict__ x,
                                                 const float* __restrict__ bias,
                                                 float* __restrict__ C,
                                                 int K, int ldc, int mode) {
    extern __shared__ float sm[];
    float* As = sm;                         // [2][128][36]
    float* Bs = sm + 2 * 128 * 36;          // [2][256][36]
    __shared__ float sred[128], sqred[128];
    int tid = threadIdx.x, lane = tid & 31, warp = tid >> 5;
    int r8 = lane & 7, g = lane >> 3;
    int qr = lane >> 2, qc = lane & 3;
    int wm = warp >> 2, wn = warp & 3;
    int t0 = blockIdx.x * 128, n0 = blockIdx.y * 256;
    int seq0 = t0 & ~(LSEQ - 1);
    int NC = K >> 5;

    uint32_t as_u = s2u(As), bs_u = s2u(Bs);
    uint32_t a_frag = as_u + ((wm * 32 + r8 + (g & 1) * 8) * 36 + (g >> 1) * 4) * 4;
    uint32_t b_frag = bs_u + ((wn * 64 + r8 + (g >> 1) * 8) * 36 + (g & 1) * 4) * 4;

    float cacc[2][8][4];
    #pragma unroll
    for (int mt = 0; mt < 2; mt++)
        #pragma unroll
        for (int nt = 0; nt < 8; nt++)
            #pragma unroll
            for (int i = 0; i < 4; i++) cacc[mt][nt][i] = 0.f;

    gemm_prefetch(A, B, as_u, bs_u, 0, K, t0, n0, seq0, mode, tid);
    for (int c = 0; c < NC; c++) {
        if (c + 1 < NC) {
            gemm_prefetch(A, B, as_u, bs_u, c + 1, K, t0, n0, seq0, mode, tid);
            asm volatile("cp.async.wait_group 1;" ::: "memory");
        } else {
            asm volatile("cp.async.wait_group 0;" ::: "memory");
        }
        __syncthreads();
        int b = c & 1;
        uint32_t af = a_frag + b * 128 * 36 * 4;
        uint32_t bf = b_frag + b * 256 * 36 * 4;
        #pragma unroll
        for (int ks = 0; ks < 4; ks++) {
            uint32_t a0[4], a1[4], bb[4][4];
            ldsm4(a0, af + ks * 32);
            ldsm4(a1, af + 16 * 36 * 4 + ks * 32);
            #pragma unroll
            for (int n2 = 0; n2 < 4; n2++) ldsm4(bb[n2], bf + n2 * 16 * 36 * 4 + ks * 32);
            #pragma unroll
            for (int n2 = 0; n2 < 4; n2++) {
                mma8(cacc[0][n2 * 2],     a0, &bb[n2][0]);
                mma8(cacc[0][n2 * 2 + 1], a0, &bb[n2][2]);
                mma8(cacc[1][n2 * 2],     a1, &bb[n2][0]);
                mma8(cacc[1][n2 * 2 + 1], a1, &bb[n2][2]);
            }
        }
        __syncthreads();
    }

    if (mode == 1) {
        #pragma unroll
        for (int mt = 0; mt < 2; mt++)
            #pragma unroll
            for (int nt = 0; nt < 8; nt++) {
                int r = t0 + wm * 32 + mt * 16 + qr;
                int col = n0 + wn * 64 + nt * 8 + qc * 2;
                *(float2*)(C + (size_t)r * ldc + col) =
                    make_float2(ftf(cacc[mt][nt][0]), ftf(cacc[mt][nt][1]));
                *(float2*)(C + (size_t)(r + 8) * ldc + col) =
                    make_float2(ftf(cacc[mt][nt][2]), ftf(cacc[mt][nt][3]));
            }
        return;
    }

    // ---- fused bias (+residual/leaky) + LN epilogue ----
    if (tid < 128) { sred[tid] = 0.f; sqred[tid] = 0.f; }
    __syncthreads();

    float bcol[8][2];
    #pragma unroll
    for (int nt = 0; nt < 8; nt++) {
        float2 b2 = *(const float2*)(bias + wn * 64 + nt * 8 + qc * 2);
        bcol[nt][0] = b2.x; bcol[nt][1] = b2.y;
    }
    float s1[4] = {0.f, 0.f, 0.f, 0.f}, sq[4] = {0.f, 0.f, 0.f, 0.f};
    #pragma unroll
    for (int mt = 0; mt < 2; mt++)
        #pragma unroll
        for (int h2 = 0; h2 < 2; h2++) {
            int rr = mt * 2 + h2;
            int r = wm * 32 + mt * 16 + h2 * 8 + qr;
            #pragma unroll
            for (int nt = 0; nt < 8; nt++) {
                float y0 = cacc[mt][nt][h2 * 2] + bcol[nt][0];
                float y1 = cacc[mt][nt][h2 * 2 + 1] + bcol[nt][1];
                if (mode == 0) {
                    float2 rx = *(const float2*)(x + (size_t)(t0 + r) * 256 +
                                                 wn * 64 + nt * 8 + qc * 2);
                    y0 += rx.x; y1 += rx.y;
                    y0 = y0 > 0.f ? y0 : 0.01f * y0;
                    y1 = y1 > 0.f ? y1 : 0.01f * y1;
                }
                cacc[mt][nt][h2 * 2] = y0;
                cacc[mt][nt][h2 * 2 + 1] = y1;
                s1[rr] += y0 + y1;
                sq[rr] += y0 * y0 + y1 * y1;
            }
        }
    #pragma unroll
    for (int o = 1; o <= 2; o <<= 1)
        #pragma unroll
        for (int rr = 0; rr < 4; rr++) {
            s1[rr] += __shfl_xor_sync(0xffffffffu, s1[rr], o);
            sq[rr] += __shfl_xor_sync(0xffffffffu, sq[rr], o);
        }
    if (qc == 0) {
        #pragma unroll
        for (int rr = 0; rr < 4; rr++) {
            int r = wm * 32 + (rr >> 1) * 16 + (rr & 1) * 8 + qr;
            atomicAdd(&sred[r], s1[rr]);
            atomicAdd(&sqred[r], sq[rr]);
        }
    }
    __syncthreads();
    #pragma unroll
    for (int mt = 0; mt < 2; mt++)
        #pragma unroll
        for (int h2 = 0; h2 < 2; h2++) {
            int r = wm * 32 + mt * 16 + h2 * 8 + qr;
            float mu = sred[r] * (1.f / DD);
            float inv = rsqrtf(sqred[r] * (1.f / DD) - mu * mu + EPSL);
            #pragma unroll
            for (int nt = 0; nt < 8; nt++) {
                int col = wn * 64 + nt * 8 + qc * 2;
                float y0 = (cacc[mt][nt][h2 * 2] - mu) * inv;
                float y1 = (cacc[mt][nt][h2 * 2 + 1] - mu) * inv;
                if (mode == 0) { y0 = ftf(y0); y1 = ftf(y1); }
                *(float2*)(C + (size_t)(t0 + r) * ldc + col) = make_float2(y0, y1);
            }
        }
}

// ---------- fused attention per (128 rows, head), 256 threads ----------
__global__ void __launch_bounds__(256) k_attn() {
    extern __shared__ float sm[];
    float* Aq = sm;                   // [128][68]
    float* Bk = Aq + 128 * 68;        // [128][68]
    float* P  = Bk + 128 * 68;        // [128][132]
    float* Bv = P + 128 * 132;        // [64][132]
    float* rs = Bv + 64 * 132;        // [128]
    int tid = threadIdx.x, lane = tid & 31, warp = tid >> 5;
    int qr = lane >> 2, qc = lane & 3;
    int wm = warp >> 1, wn = warp & 1;
    int t0 = blockIdx.x * 128, h = blockIdx.y;

    for (int i = tid; i < 2048; i += 256) {
        int r = i >> 4, cc = i & 15;
        *(float4*)(Aq + r * 68 + cc * 4) =
            *(const float4*)(g_q + (size_t)(t0 + r) * 512 + h * 64 + cc * 4);
    }
    if (tid < 128) rs[tid] = 0.f;

    float oacc[2][4][4];
    #pragma unroll
    for (int mt = 0; mt < 2; mt++)
        #pragma unroll
        for (int nt = 0; nt < 4; nt++)
            #pragma unroll
            for (int i = 0; i < 4; i++) oacc[mt][nt][i] = 0.f;

    for (int c = 0; c < 4; c++) {
        __syncthreads();
        for (int i = tid; i < 2048; i += 256) {
            int r = i >> 4, cc = i & 15;
            *(float4*)(Bk + r * 68 + cc * 4) =
                *(const float4*)(g_k + ((size_t)h * PP + c * 128 + r) * 64 + cc * 4);
        }
        for (int i = tid; i < 2048; i += 256) {
            int r = i >> 5, cc = i & 31;
            *(float4*)(Bv + r * 132 + cc * 4) =
                *(const float4*)(g_vT + ((size_t)h * 64 + r) * PP + c * 128 + cc * 4);
        }
        __syncthreads();

        float s[2][8][4];
        #pragma unroll
        for (int mt = 0; mt < 2; mt++)
            #pragma unroll
            for (int nt = 0; nt < 8; nt++)
                #pragma unroll
                for (int i = 0; i < 4; i++) s[mt][nt][i] = 0.f;
        #pragma unroll
        for (int ks = 0; ks < 8; ks++) {
            int k0 = ks * 8;
            uint32_t a[2][4], b[8][2];
            #pragma unroll
            for (int mt = 0; mt < 2; mt++) {
                int m0 = wm * 32 + mt * 16;
                a[mt][0] = FB(Aq[(m0 + qr) * 68 + k0 + qc]);
                a[mt][1] = FB(Aq[(m0 + qr + 8) * 68 + k0 + qc]);
                a[mt][2] = FB(Aq[(m0 + qr) * 68 + k0 + qc + 4]);
                a[mt][3] = FB(Aq[(m0 + qr + 8) * 68 + k0 + qc + 4]);
            }
            #pragma unroll
            for (int nt = 0; nt < 8; nt++) {
                int nb = wn * 64 + nt * 8;
                b[nt][0] = FB(Bk[(nb + qr) * 68 + k0 + qc]);
                b[nt][1] = FB(Bk[(nb + qr) * 68 + k0 + qc + 4]);
            }
            #pragma unroll
            for (int mt = 0; mt < 2; mt++)
                #pragma unroll
                for (int nt = 0; nt < 8; nt++) mma8(s[mt][nt], a[mt], b[nt]);
        }

        #pragma unroll
        for (int mt = 0; mt < 2; mt++) {
            int r = wm * 32 + mt * 16 + qr;
            float sum0 = 0.f, sum1 = 0.f;
            #pragma unroll
            for (int nt = 0; nt < 8; nt++) {
                float e0 = __expf(s[mt][nt][0]);
                float e1 = __expf(s[mt][nt][1]);
                float e2 = __expf(s[mt][nt][2]);
                float e3 = __expf(s[mt][nt][3]);
                sum0 += e0 + e1;
                sum1 += e2 + e3;
                int col = wn * 64 + nt * 8 + qc * 2;
                *(float2*)(P + r * 132 + col) = make_float2(ftf(e0), ftf(e1));
                *(float2*)(P + (r + 8) * 132 + col) = make_float2(ftf(e2), ftf(e3));
            }
            sum0 += __shfl_xor_sync(0xffffffffu, sum0, 1);
            sum0 += __shfl_xor_sync(0xffffffffu, sum0, 2);
            sum1 += __shfl_xor_sync(0xffffffffu, sum1, 1);
            sum1 += __shfl_xor_sync(0xffffffffu, sum1, 2);
            if (qc == 0) {
                atomicAdd(&rs[r], sum0);
                atomicAdd(&rs[r + 8], sum1);
            }
        }
        __syncthreads();

        #pragma unroll
        for (int ks = 0; ks < 16; ks++) {
            int k0 = ks * 8;
            uint32_t a[2][4], b[4][2];
            #pragma unroll
            for (int mt = 0; mt < 2; mt++) {
                int m0 = wm * 32 + mt * 16;
                a[mt][0] = FB(P[(m0 + qr) * 132 + k0 + qc]);
                a[mt][1] = FB(P[(m0 + qr + 8) * 132 + k0 + qc]);
                a[mt][2] = FB(P[(m0 + qr) * 132 + k0 + qc + 4]);
                a[mt][3] = FB(P[(m0 + qr + 8) * 132 + k0 + qc + 4]);
            }
            #pragma unroll
            for (int nt = 0; nt < 4; nt++) {
                int nb = wn * 32 + nt * 8;
                b[nt][0] = FB(Bv[(nb + qr) * 132 + k0 + qc]);
                b[nt][1] = FB(Bv[(nb + qr) * 132 + k0 + qc + 4]);
            }
            #pragma unroll
            for (int mt = 0; mt < 2; mt++)
                #pragma unroll
                for (int nt = 0; nt < 4; nt++) mma8(oacc[mt][nt], a[mt], b[nt]);
        }
    }
    __syncthreads();

    #pragma unroll
    for (int mt = 0; mt < 2; mt++)
        #pragma unroll
        for (int nt = 0; nt < 4; nt++) {
            int r = wm * 32 + mt * 16 + qr;
            int col = wn * 32 + nt * 8 + qc * 2;
            float i0 = 1.f / rs[r], i1 = 1.f / rs[r + 8];
            *(float2*)(g_att + (size_t)(t0 + r) * 512 + h * 64 + col) =
                make_float2(ftf(oacc[mt][nt][0] * i0), ftf(oacc[mt][nt][1] * i0));
            *(float2*)(g_att + (size_t)(t0 + r + 8) * 512 + h * 64 + col) =
                make_float2(ftf(oacc[mt][nt][2] * i1), ftf(oacc[mt][nt][3] * i1));
        }
}

extern "C" void kernel_launch(void* const* d_in, const int* in_sizes, int n_in,
                              void* d_out, int out_size) {
    const float* x      = (const float*)d_in[0];
    const float* conv_w = (const float*)d_in[1];
    const float* conv_b = (const float*)d_in[2];
    const float* pat    = (const float*)d_in[3];
    const float* wq     = (const float*)d_in[4];
    const float* wkv    = (const float*)d_in[5];
    const float* wout   = (const float*)d_in[6];
    const float* bout   = (const float*)d_in[7];
    float* out = (float*)d_out;

    const int GEMM_SMEM = (2 * 128 * 36 + 2 * 256 * 36) * 4;              // 110592
    const int ATTN_SMEM = (128*68 + 128*68 + 128*132 + 64*132 + 128) * 4; // 171520
    cudaFuncSetAttribute(k_gemm, cudaFuncAttributeMaxDynamicSharedMemorySize, GEMM_SMEM);
    cudaFuncSetAttribute(k_attn, cudaFuncAttributeMaxDynamicSharedMemorySize, ATTN_SMEM);

    float* p_wcat; cudaGetSymbolAddress((void**)&p_wcat, g_wcat);
    float* p_wq;   cudaGetSymbolAddress((void**)&p_wq, g_wq);
    float* p_wo;   cudaGetSymbolAddress((void**)&p_wo, g_wo);
    float* p_xr;   cudaGetSymbolAddress((void**)&p_xr, g_xr);
    float* p_xln;  cudaGetSymbolAddress((void**)&p_xln, g_xln);
    float* p_q;    cudaGetSymbolAddress((void**)&p_q, g_q);
    float* p_att;  cudaGetSymbolAddress((void**)&p_att, g_att);

    k_prep<<<768, 256>>>(conv_w, wq, wout);
    k_prepx<<<16384, 256>>>(x);
    k_patkv<<<64, 256>>>(pat, wkv);
    // conv: A=g_xr (taps), B=g_wcat, fused bias+res+leaky+LN -> g_xln (tf32)
    k_gemm<<<512, 512, GEMM_SMEM>>>(p_xr, p_wcat, x, conv_b, p_xln, 768, 256, 0);
    // q: A=g_xln, B=g_wq (two 256-col blocks)
    k_gemm<<<dim3(512, 2), 512, GEMM_SMEM>>>(p_xln, p_wq, nullptr, nullptr, p_q, 256, 512, 1);
    k_attn<<<dim3(512, 8), 256, ATTN_SMEM>>>();
    // out: A=g_att (tf32 already), B=g_wo, fused bias+LN -> out
    k_gemm<<<512, 512, GEMM_SMEM>>>(p_att, p_wo, nullptr, bout, out, 512, 256, 2);
}